// round 11
// baseline (speedup 1.0000x reference)
#include <cuda_runtime.h>
#include <cuda_fp16.h>
#include <math.h>

#define B_ 16
#define T_ 512
#define D_ 256
#define H_ 8
#define E_ 32
#define BASIS_ 8
#define HB_ 128          // H_*B_
#define HE_ 256          // H_*E_

// ---------------- scratch (static device globals; no allocation) ----------------
__device__ float   g_qw[T_*BASIS_];
__device__ float   g_kw[T_*BASIS_];
__device__ __half2 g_Qt16[T_*D_*HE_/2];    // 67MB
__device__ __half2 g_Kt16[T_*D_*HE_/2];    // 67MB
__device__ float   g_q[HB_*T_*E_];         // [h][b][t][e] fp32
__device__ float   g_k[HB_*T_*E_];
__device__ __half2 g_v16[HB_*T_*E_/2];     // [h][b][t][e] fp16
__device__ __half2 g_lamA2[T_*256];
__device__ __half2 g_oml2[T_*256];

// ---------------- K1: per-token basis mixing weights ----------------
__global__ void k1_weights(const float* __restrict__ te,
                           const float* __restrict__ Wq,
                           const float* __restrict__ Wk) {
    int t = blockIdx.x;
    int warp = threadIdx.x >> 5, lane = threadIdx.x & 31;
    const float* tr = te + t * D_;
    const float* wq = Wq + (t * BASIS_ + warp) * D_;
    const float* wk = Wk + (t * BASIS_ + warp) * D_;
    float aq = 0.f, ak = 0.f;
    #pragma unroll
    for (int m = 0; m < D_ / 32; ++m) {
        int d = lane + 32 * m;
        float x = tr[d];
        aq += x * wq[d];
        ak += x * wk[d];
    }
    #pragma unroll
    for (int o = 16; o; o >>= 1) {
        aq += __shfl_xor_sync(0xffffffffu, aq, o);
        ak += __shfl_xor_sync(0xffffffffu, ak, o);
    }
    if (lane == 0) {
        g_qw[t * BASIS_ + warp] = aq;
        g_kw[t * BASIS_ + warp] = ak;
    }
}

// ---------------- K2: Q_tilde / K_tilde build (fp16 out), t-chunked ----------------
__global__ __launch_bounds__(256) void k2_tilde(const float* __restrict__ Qb,
                                                const float* __restrict__ Kb) {
    __shared__ float sW[64 * BASIS_];
    int qk = blockIdx.y;
    int t0 = blockIdx.z << 6;
    const float* W = (qk ? g_kw : g_qw) + t0 * BASIS_;
    const float* Bs = qk ? Kb : Qb;
    uint2* Out = qk ? (uint2*)g_Kt16 : (uint2*)g_Qt16;
    for (int idx = threadIdx.x; idx < 64 * BASIS_; idx += 256) sW[idx] = W[idx];
    __syncthreads();

    int f4 = blockIdx.x * 256 + threadIdx.x;
    float4 b4[BASIS_];
    #pragma unroll
    for (int k = 0; k < BASIS_; ++k) b4[k] = ((const float4*)Bs)[k * 16384 + f4];

    for (int tt = 0; tt < 64; ++tt) {
        float4 a = make_float4(0.f, 0.f, 0.f, 0.f);
        #pragma unroll
        for (int k = 0; k < BASIS_; ++k) {
            float w = sW[tt * BASIS_ + k];
            a.x += w * b4[k].x; a.y += w * b4[k].y;
            a.z += w * b4[k].z; a.w += w * b4[k].w;
        }
        __half2 h0 = __floats2half2_rn(a.x, a.y);
        __half2 h1 = __floats2half2_rn(a.z, a.w);
        uint2 u;
        u.x = *(const unsigned int*)&h0;
        u.y = *(const unsigned int*)&h1;
        Out[(t0 + tt) * 16384 + f4] = u;
    }
}

// ---------------- K3: q/k/v projections, MLP-8 batched loads ----------------
// grid (T, 3): m=0 Q, m=1 K (fp16 W, 8 cols/thread), m=2 V (fp32 W, 8 cols/thread)
__global__ __launch_bounds__(256) void k3_qkv(const float* __restrict__ X,
                                              const float* __restrict__ WV) {
    __shared__ float xsT[D_][16];
    int t = blockIdx.x, m = blockIdx.y;

    for (int idx = threadIdx.x; idx < B_ * D_; idx += 256) {
        int b = idx >> 8, d = idx & 255;
        xsT[d][b] = X[((size_t)b * T_ + t) * D_ + d];
    }
    __syncthreads();

    int tc = threadIdx.x & 31;   // col group: cols [8tc, 8tc+8)
    int tb = threadIdx.x >> 5;   // b pair: 2tb, 2tb+1

    float acc[2][8];
    #pragma unroll
    for (int i = 0; i < 2; ++i)
        #pragma unroll
        for (int j = 0; j < 8; ++j) acc[i][j] = 0.f;

    if (m < 2) {
        const uint4* W = (const uint4*)((m == 0 ? g_Qt16 : g_Kt16) + (size_t)t * 32768);
        for (int d0 = 0; d0 < D_; d0 += 8) {
            uint4 wr[8];
            #pragma unroll
            for (int i = 0; i < 8; ++i) wr[i] = W[((d0 + i) << 5) + tc];
            #pragma unroll
            for (int i = 0; i < 8; ++i) {
                float2 xv = *(const float2*)&xsT[d0 + i][tb << 1];
                float2 w0 = __half22float2(*(const __half2*)&wr[i].x);
                float2 w1 = __half22float2(*(const __half2*)&wr[i].y);
                float2 w2 = __half22float2(*(const __half2*)&wr[i].z);
                float2 w3 = __half22float2(*(const __half2*)&wr[i].w);
                acc[0][0] += xv.x * w0.x; acc[0][1] += xv.x * w0.y;
                acc[0][2] += xv.x * w1.x; acc[0][3] += xv.x * w1.y;
                acc[0][4] += xv.x * w2.x; acc[0][5] += xv.x * w2.y;
                acc[0][6] += xv.x * w3.x; acc[0][7] += xv.x * w3.y;
                acc[1][0] += xv.y * w0.x; acc[1][1] += xv.y * w0.y;
                acc[1][2] += xv.y * w1.x; acc[1][3] += xv.y * w1.y;
                acc[1][4] += xv.y * w2.x; acc[1][5] += xv.y * w2.y;
                acc[1][6] += xv.y * w3.x; acc[1][7] += xv.y * w3.y;
            }
        }
        float* Out = (m == 0) ? g_q : g_k;
        int e0 = tc << 3;
        int h = e0 >> 5, eo = e0 & 31;
        #pragma unroll
        for (int i = 0; i < 2; ++i) {
            int b = (tb << 1) + i;
            size_t base = (((size_t)(h * B_ + b) * T_ + t) << 5) + eo;
            *(float4*)&Out[base]     = make_float4(acc[i][0], acc[i][1], acc[i][2], acc[i][3]);
            *(float4*)&Out[base + 4] = make_float4(acc[i][4], acc[i][5], acc[i][6], acc[i][7]);
        }
    } else {
        const float* W = WV + (size_t)t * 65536;
        int e0 = tc << 3;
        for (int d0 = 0; d0 < D_; d0 += 4) {
            float4 wa[4], wb[4];
            #pragma unroll
            for (int i = 0; i < 4; ++i) {
                wa[i] = *(const float4*)&W[((d0 + i) << 8) + e0];
                wb[i] = *(const float4*)&W[((d0 + i) << 8) + e0 + 4];
            }
            #pragma unroll
            for (int i = 0; i < 4; ++i) {
                float2 xv = *(const float2*)&xsT[d0 + i][tb << 1];
                acc[0][0] += xv.x * wa[i].x; acc[0][1] += xv.x * wa[i].y;
                acc[0][2] += xv.x * wa[i].z; acc[0][3] += xv.x * wa[i].w;
                acc[0][4] += xv.x * wb[i].x; acc[0][5] += xv.x * wb[i].y;
                acc[0][6] += xv.x * wb[i].z; acc[0][7] += xv.x * wb[i].w;
                acc[1][0] += xv.y * wa[i].x; acc[1][1] += xv.y * wa[i].y;
                acc[1][2] += xv.y * wa[i].z; acc[1][3] += xv.y * wa[i].w;
                acc[1][4] += xv.y * wb[i].x; acc[1][5] += xv.y * wb[i].y;
                acc[1][6] += xv.y * wb[i].z; acc[1][7] += xv.y * wb[i].w;
            }
        }
        int h = e0 >> 5, eo = e0 & 31;
        #pragma unroll
        for (int i = 0; i < 2; ++i) {
            int b = (tb << 1) + i;
            __half2 p0 = __floats2half2_rn(acc[i][0], acc[i][1]);
            __half2 p1 = __floats2half2_rn(acc[i][2], acc[i][3]);
            __half2 p2 = __floats2half2_rn(acc[i][4], acc[i][5]);
            __half2 p3 = __floats2half2_rn(acc[i][6], acc[i][7]);
            uint4 u;
            u.x = *(const unsigned int*)&p0;
            u.y = *(const unsigned int*)&p1;
            u.z = *(const unsigned int*)&p2;
            u.w = *(const unsigned int*)&p3;
            *(uint4*)&g_v16[(((size_t)(h * B_ + b) * T_ + t) << 4) + (eo >> 1)] = u;
        }
    }
}

// ---------------- K4: mixing coefficients (half2 out) ----------------
__global__ void k4_mix(const float* __restrict__ A, const float* __restrict__ L) {
    int t = blockIdx.x, c = threadIdx.x;
    int j0 = c << 1, j1 = j0 + 1;
    float a0 = 0.5f * (A[t * T_ + j0] + A[j0 * T_ + t]);
    float a1 = 0.5f * (A[t * T_ + j1] + A[j1 * T_ + t]);
    float lam0 = 1.0f / (1.0f + __expf(-L[t * T_ + j0]));
    float lam1 = 1.0f / (1.0f + __expf(-L[t * T_ + j1]));
    g_lamA2[t * 256 + c] = __floats2half2_rn(lam0 * a0, lam1 * a1);
    g_oml2[t * 256 + c]  = __floats2half2_rn(1.0f - lam0, 1.0f - lam1);
}

// ---------------- K57: fused scores+softmax+mix+symexp+Sinkhorn+PV ----------------
#define SM_UNION 131072
#define SM_Y     196864
#define SM_UL    200960
#define SMEM57   201472
#define NW_      32       // warps per CTA

#define CBAR() do { \
    asm volatile("barrier.cluster.arrive.aligned;" ::: "memory"); \
    asm volatile("barrier.cluster.wait.aligned;"  ::: "memory"); } while (0)

__global__ __launch_bounds__(1024) __cluster_dims__(4, 1, 1)
void k57(float* __restrict__ out) {
    extern __shared__ char sm[];
    __half2* tile = (__half2*)sm;                 // [128][256] half2 = M/E rows fp16
    float2*  kT2  = (float2*)(sm + SM_UNION);     // [32][257] float2 (phase 1-2)
    float*   Vs   = (float*)(sm + SM_UNION);      // [512][32] f32 (phase 5-6)
    float*   s_y  = (float*)(sm + SM_Y);          // [2][512]
    float*   s_ul = (float*)(sm + SM_UL);         // [128]

    int tid = threadIdx.x;
    int hb = blockIdx.x >> 2;
    int rank = blockIdx.x & 3;
    int warp = tid >> 5, lane = tid & 31;

    unsigned sbase;
    asm("{ .reg .u64 t; cvta.to.shared.u64 t, %1; cvt.u32.u64 %0, t; }"
        : "=r"(sbase) : "l"(sm));

    // ---- phase 1: K transpose into kT2 ----
    const float* K = g_k + hb * (T_ * E_);
    for (int idx = tid; idx < T_ * E_; idx += 1024) {
        int t = idx >> 5, e = idx & 31;
        ((float*)&kT2[e * 257 + (t >> 1)])[t & 1] = K[idx];
    }
    __syncthreads();

    // ---- phase 2: scores + softmax + mix -> tile (fp16 M, local rows) ----
    {
        const float* Q = g_q + hb * (T_ * E_);
        const float SC = 0.17677669529663687f;
        for (int p = warp; p < 64; p += NW_) {
            int i0 = p << 1, i1 = i0 + 1;
            int gi0 = (rank << 7) + i0, gi1 = gi0 + 1;
            float q0 = Q[(gi0 << 5) + lane];
            float q1 = Q[(gi1 << 5) + lane];
            float a[8][4];
            #pragma unroll
            for (int m = 0; m < 8; ++m) { a[m][0] = a[m][1] = a[m][2] = a[m][3] = 0.f; }
            #pragma unroll
            for (int d = 0; d < 32; ++d) {
                float qd0 = __shfl_sync(0xffffffffu, q0, d);
                float qd1 = __shfl_sync(0xffffffffu, q1, d);
                const float2* row = &kT2[d * 257];
                #pragma unroll
                for (int m = 0; m < 8; ++m) {
                    float2 kv = row[lane + (m << 5)];
                    a[m][0] += qd0 * kv.x; a[m][1] += qd0 * kv.y;
                    a[m][2] += qd1 * kv.x; a[m][3] += qd1 * kv.y;
                }
            }
            float mx0 = -1e30f, mx1 = -1e30f;
            #pragma unroll
            for (int m = 0; m < 8; ++m) {
                a[m][0] *= SC; a[m][1] *= SC; a[m][2] *= SC; a[m][3] *= SC;
                mx0 = fmaxf(mx0, fmaxf(a[m][0], a[m][1]));
                mx1 = fmaxf(mx1, fmaxf(a[m][2], a[m][3]));
            }
            #pragma unroll
            for (int o = 16; o; o >>= 1) {
                mx0 = fmaxf(mx0, __shfl_xor_sync(0xffffffffu, mx0, o));
                mx1 = fmaxf(mx1, __shfl_xor_sync(0xffffffffu, mx1, o));
            }
            float sm0 = 0.f, sm1 = 0.f;
            #pragma unroll
            for (int m = 0; m < 8; ++m) {
                a[m][0] = __expf(a[m][0] - mx0); a[m][1] = __expf(a[m][1] - mx0);
                a[m][2] = __expf(a[m][2] - mx1); a[m][3] = __expf(a[m][3] - mx1);
                sm0 += a[m][0] + a[m][1];
                sm1 += a[m][2] + a[m][3];
            }
            #pragma unroll
            for (int o = 16; o; o >>= 1) {
                sm0 += __shfl_xor_sync(0xffffffffu, sm0, o);
                sm1 += __shfl_xor_sync(0xffffffffu, sm1, o);
            }
            float in0 = 1.0f / sm0, in1 = 1.0f / sm1;
            #pragma unroll
            for (int m = 0; m < 8; ++m) {
                int c = lane + (m << 5);
                float2 la0 = __half22float2(g_lamA2[gi0 * 256 + c]);
                float2 om0 = __half22float2(g_oml2[gi0 * 256 + c]);
                float2 la1 = __half22float2(g_lamA2[gi1 * 256 + c]);
                float2 om1 = __half22float2(g_oml2[gi1 * 256 + c]);
                tile[(i0 << 8) + c] = __floats2half2_rn(la0.x + om0.x * (a[m][0] * in0),
                                                        la0.y + om0.y * (a[m][1] * in0));
                tile[(i1 << 8) + c] = __floats2half2_rn(la1.x + om1.x * (a[m][2] * in1),
                                                        la1.y + om1.y * (a[m][3] * in1));
            }
        }
    }
    __syncthreads();
    CBAR();   // all cluster tiles hold M

    // ---- phase 3: symmetrize + exp (DSMEM peer reads, reg-staged) ----
    {
        int i0 = (tid & 15) << 3;    // 8 rows
        int j0 = (tid >> 4) << 3;    // 8 cols (64 groups)
        uint4 pv[8];
        #pragma unroll
        for (int jj = 0; jj < 8; ++jj) {
            int j = j0 + jj;
            unsigned laddr = sbase + (unsigned)((((j & 127) << 9) + (rank << 7) + i0) << 1);
            unsigned raddr;
            asm volatile("mapa.shared::cluster.u32 %0, %1, %2;"
                         : "=r"(raddr) : "r"(laddr), "r"(j >> 7));
            asm volatile("ld.shared::cluster.v4.u32 {%0,%1,%2,%3}, [%4];"
                         : "=r"(pv[jj].x), "=r"(pv[jj].y), "=r"(pv[jj].z), "=r"(pv[jj].w)
                         : "r"(raddr));
        }
        CBAR();   // all reads done -> safe to overwrite
        #pragma unroll
        for (int ii = 0; ii < 8; ++ii) {
            int i = i0 + ii;
            __half2* rowp = &tile[(i << 8) + (j0 >> 1)];
            uint4 o0 = *(const uint4*)rowp;
            __half oh[8];
            *(uint4*)&oh[0] = o0;
            __half rh[8];
            #pragma unroll
            for (int jj = 0; jj < 8; ++jj) {
                float pe = __half2float(((const __half*)&pv[jj])[ii]);
                float ow = __half2float(oh[jj]);
                rh[jj] = __float2half_rn(__expf(0.5f * (ow + pe)));
            }
            *(uint4*)rowp = *(const uint4*)&rh[0];
        }
    }
    if (tid < 512) s_y[tid] = 1.0f;   // buffer 0 = ev_init
    __syncthreads();

    // ---- phase 4: Sinkhorn, 40 half-steps (uint4 + HFMA2 chunks) ----
    int cur = 0;
    for (int hstep = 0; hstep < 40; ++hstep) {
        const float* yb = &s_y[cur << 9];
        float4 ya0 = *(const float4*)&yb[lane * 8];
        float4 ya1 = *(const float4*)&yb[lane * 8 + 4];
        float4 yb0 = *(const float4*)&yb[256 + lane * 8];
        float4 yb1 = *(const float4*)&yb[256 + lane * 8 + 4];
        __half2 yh0 = __floats2half2_rn(ya0.x, ya0.y);
        __half2 yh1 = __floats2half2_rn(ya0.z, ya0.w);
        __half2 yh2 = __floats2half2_rn(ya1.x, ya1.y);
        __half2 yh3 = __floats2half2_rn(ya1.z, ya1.w);
        __half2 yh4 = __floats2half2_rn(yb0.x, yb0.y);
        __half2 yh5 = __floats2half2_rn(yb0.z, yb0.w);
        __half2 yh6 = __floats2half2_rn(yb1.x, yb1.y);
        __half2 yh7 = __floats2half2_rn(yb1.z, yb1.w);

        int nxt = cur ^ 1;
        for (int i = warp; i < 128; i += NW_) {
            const uint4* rowq = (const uint4*)(tile + (i << 8));
            uint4 ea = rowq[lane];
            uint4 eb = rowq[lane + 32];
            __half2 a0 = __hmul2(*(const __half2*)&ea.x, yh0);
            a0 = __hfma2(*(const __half2*)&ea.y, yh1, a0);
            a0 = __hfma2(*(const __half2*)&ea.z, yh2, a0);
            a0 = __hfma2(*(const __half2*)&ea.w, yh3, a0);
            __half2 a1 = __hmul2(*(const __half2*)&eb.x, yh4);
            a1 = __hfma2(*(const __half2*)&eb.y, yh5, a1);
            a1 = __hfma2(*(const __half2*)&eb.z, yh6, a1);
            a1 = __hfma2(*(const __half2*)&eb.w, yh7, a1);
            float2 f0 = __half22float2(a0);
            float2 f1 = __half22float2(a1);
            float acc = f0.x + f0.y + f1.x + f1.y;
            #pragma unroll
            for (int o = 16; o; o >>= 1) acc += __shfl_xor_sync(0xffffffffu, acc, o);
            if (lane == 0) {
                float r = 1.0f / acc;
                if (!(hstep & 1)) s_ul[i] = r;
                unsigned laddr = sbase + (unsigned)(SM_Y + (((nxt << 9) + (rank << 7) + i) << 2));
                #pragma unroll
                for (int tr = 0; tr < 4; ++tr) {
                    unsigned raddr;
                    asm volatile("mapa.shared::cluster.u32 %0, %1, %2;"
                                 : "=r"(raddr) : "r"(laddr), "r"(tr));
                    asm volatile("st.shared::cluster.f32 [%0], %1;"
                                 :: "r"(raddr), "f"(r) : "memory");
                }
            }
        }
        CBAR();
        cur ^= 1;
    }
    // s_y[cur] = final ev (512), s_ul = final eu (local 128)

    // ---- phase 5: Vs fp32 = V * ev ----
    {
        const __half2* V16 = g_v16 + hb * 8192;
        const float* evf = &s_y[cur << 9];
        for (int idx = tid; idx < 8192; idx += 1024) {
            int j = idx >> 4, c2 = idx & 15;
            float2 v = __half22float2(V16[idx]);
            float e = evf[j];
            Vs[(j << 5) + (c2 << 1)]     = v.x * e;
            Vs[(j << 5) + (c2 << 1) + 1] = v.y * e;
        }
    }
    __syncthreads();

    // ---- phase 6: out = eu * (E @ Vs), 4 rows per warp ----
    {
        float acc[4];
        #pragma unroll
        for (int r = 0; r < 4; ++r) acc[r] = 0.f;
        const __half2* trow = tile + ((warp << 2) << 8);
        #pragma unroll 2
        for (int c = 0; c < 256; ++c) {
            float vx = Vs[((c << 1) << 5) + lane];
            float vy = Vs[(((c << 1) + 1) << 5) + lane];
            #pragma unroll
            for (int r = 0; r < 4; ++r) {
                float2 p = __half22float2(trow[(r << 8) + c]);
                acc[r] += p.x * vx + p.y * vy;
            }
        }
        int h = hb >> 4, b = hb & 15;
        #pragma unroll
        for (int r = 0; r < 4; ++r) {
            int gi = (rank << 7) + (warp << 2) + r;
            out[(((size_t)(b * T_ + gi)) << 8) + (h << 5) + lane]
                = s_ul[(warp << 2) + r] * acc[r];
        }
    }
}

// ---------------- launch ----------------
extern "C" void kernel_launch(void* const* d_in, const int* in_sizes, int n_in,
                              void* d_out, int out_size) {
    const float* X  = (const float*)d_in[0];
    const float* te = (const float*)d_in[1];
    const float* Wq = (const float*)d_in[2];
    const float* Wk = (const float*)d_in[3];
    const float* Qb = (const float*)d_in[4];
    const float* Kb = (const float*)d_in[5];
    const float* WV = (const float*)d_in[6];
    const float* A  = (const float*)d_in[7];
    const float* L  = (const float*)d_in[8];
    float* out = (float*)d_out;

    cudaFuncSetAttribute(k57, cudaFuncAttributeMaxDynamicSharedMemorySize, SMEM57);

    k1_weights<<<T_, 256>>>(te, Wq, Wk);
    k2_tilde<<<dim3(64, 2, 8), 256>>>(Qb, Kb);
    k3_qkv<<<dim3(T_, 3), 256>>>(X, WV);
    k4_mix<<<T_, 256>>>(A, L);
    k57<<<HB_ * 4, 1024, SMEM57>>>(out);
}

// round 12
// speedup vs baseline: 1.2581x; 1.2581x over previous
#include <cuda_runtime.h>
#include <cuda_fp16.h>
#include <math.h>

#define B_ 16
#define T_ 512
#define D_ 256
#define H_ 8
#define E_ 32
#define BASIS_ 8
#define HB_ 128          // H_*B_
#define HE_ 256          // H_*E_

// ---------------- scratch (static device globals; no allocation) ----------------
__device__ float   g_qw[T_*BASIS_];
__device__ float   g_kw[T_*BASIS_];
__device__ __half2 g_Qt16[T_*D_*HE_/2];    // 67MB
__device__ __half2 g_Kt16[T_*D_*HE_/2];    // 67MB
__device__ float   g_q[HB_*T_*E_];         // [h][b][t][e] fp32
__device__ float   g_k[HB_*T_*E_];
__device__ __half2 g_v16[HB_*T_*E_/2];     // [h][b][t][e] fp16
__device__ __half2 g_lamA2[T_*256];
__device__ __half2 g_oml2[T_*256];

// ---------------- K1: per-token basis mixing weights ----------------
__global__ void k1_weights(const float* __restrict__ te,
                           const float* __restrict__ Wq,
                           const float* __restrict__ Wk) {
    int t = blockIdx.x;
    int warp = threadIdx.x >> 5, lane = threadIdx.x & 31;
    const float* tr = te + t * D_;
    const float* wq = Wq + (t * BASIS_ + warp) * D_;
    const float* wk = Wk + (t * BASIS_ + warp) * D_;
    float aq = 0.f, ak = 0.f;
    #pragma unroll
    for (int m = 0; m < D_ / 32; ++m) {
        int d = lane + 32 * m;
        float x = tr[d];
        aq += x * wq[d];
        ak += x * wk[d];
    }
    #pragma unroll
    for (int o = 16; o; o >>= 1) {
        aq += __shfl_xor_sync(0xffffffffu, aq, o);
        ak += __shfl_xor_sync(0xffffffffu, ak, o);
    }
    if (lane == 0) {
        g_qw[t * BASIS_ + warp] = aq;
        g_kw[t * BASIS_ + warp] = ak;
    }
}

// ---------------- K2: Q_tilde / K_tilde build (fp16 out), t-chunked ----------------
__global__ __launch_bounds__(256) void k2_tilde(const float* __restrict__ Qb,
                                                const float* __restrict__ Kb) {
    __shared__ float sW[64 * BASIS_];
    int qk = blockIdx.y;
    int t0 = blockIdx.z << 6;
    const float* W = (qk ? g_kw : g_qw) + t0 * BASIS_;
    const float* Bs = qk ? Kb : Qb;
    uint2* Out = qk ? (uint2*)g_Kt16 : (uint2*)g_Qt16;
    for (int idx = threadIdx.x; idx < 64 * BASIS_; idx += 256) sW[idx] = W[idx];
    __syncthreads();

    int f4 = blockIdx.x * 256 + threadIdx.x;
    float4 b4[BASIS_];
    #pragma unroll
    for (int k = 0; k < BASIS_; ++k) b4[k] = ((const float4*)Bs)[k * 16384 + f4];

    for (int tt = 0; tt < 64; ++tt) {
        float4 a = make_float4(0.f, 0.f, 0.f, 0.f);
        #pragma unroll
        for (int k = 0; k < BASIS_; ++k) {
            float w = sW[tt * BASIS_ + k];
            a.x += w * b4[k].x; a.y += w * b4[k].y;
            a.z += w * b4[k].z; a.w += w * b4[k].w;
        }
        __half2 h0 = __floats2half2_rn(a.x, a.y);
        __half2 h1 = __floats2half2_rn(a.z, a.w);
        uint2 u;
        u.x = *(const unsigned int*)&h0;
        u.y = *(const unsigned int*)&h1;
        Out[(t0 + tt) * 16384 + f4] = u;
    }
}

// ---------------- K3: q/k/v projections ----------------
__global__ __launch_bounds__(256) void k3_qkv(const float* __restrict__ X,
                                              const float* __restrict__ WV) {
    __shared__ float xsT[D_][16];
    int t = blockIdx.x, m = blockIdx.y;

    for (int idx = threadIdx.x; idx < B_ * D_; idx += 256) {
        int b = idx >> 8, d = idx & 255;
        xsT[d][b] = X[((size_t)b * T_ + t) * D_ + d];
    }
    __syncthreads();

    int tc = threadIdx.x & 31;
    int tb = threadIdx.x >> 5;

    if (m < 2) {
        float acc[2][8];
        #pragma unroll
        for (int i = 0; i < 2; ++i)
            #pragma unroll
            for (int j = 0; j < 8; ++j) acc[i][j] = 0.f;
        const uint4* W = (const uint4*)((m == 0 ? g_Qt16 : g_Kt16) + (size_t)t * 32768);
        #pragma unroll 8
        for (int d = 0; d < D_; ++d) {
            float2 xv = *(const float2*)&xsT[d][tb << 1];
            uint4 wr = W[(d << 5) + tc];
            float2 w0 = __half22float2(*(const __half2*)&wr.x);
            float2 w1 = __half22float2(*(const __half2*)&wr.y);
            float2 w2 = __half22float2(*(const __half2*)&wr.z);
            float2 w3 = __half22float2(*(const __half2*)&wr.w);
            acc[0][0] += xv.x * w0.x; acc[0][1] += xv.x * w0.y;
            acc[0][2] += xv.x * w1.x; acc[0][3] += xv.x * w1.y;
            acc[0][4] += xv.x * w2.x; acc[0][5] += xv.x * w2.y;
            acc[0][6] += xv.x * w3.x; acc[0][7] += xv.x * w3.y;
            acc[1][0] += xv.y * w0.x; acc[1][1] += xv.y * w0.y;
            acc[1][2] += xv.y * w1.x; acc[1][3] += xv.y * w1.y;
            acc[1][4] += xv.y * w2.x; acc[1][5] += xv.y * w2.y;
            acc[1][6] += xv.y * w3.x; acc[1][7] += xv.y * w3.y;
        }
        float* Out = (m == 0) ? g_q : g_k;
        int e0 = tc << 3;
        int h = e0 >> 5, eo = e0 & 31;
        #pragma unroll
        for (int i = 0; i < 2; ++i) {
            int b = (tb << 1) + i;
            size_t base = (((size_t)(h * B_ + b) * T_ + t) << 5) + eo;
            *(float4*)&Out[base]     = make_float4(acc[i][0], acc[i][1], acc[i][2], acc[i][3]);
            *(float4*)&Out[base + 4] = make_float4(acc[i][4], acc[i][5], acc[i][6], acc[i][7]);
        }
    } else {
        float acc[2][4];
        #pragma unroll
        for (int i = 0; i < 2; ++i)
            #pragma unroll
            for (int j = 0; j < 4; ++j) acc[i][j] = 0.f;
        int e0 = ((m - 2) << 7) + (tc << 2);
        const float* W = WV + (size_t)t * 65536;
        #pragma unroll 8
        for (int d = 0; d < D_; ++d) {
            float2 xv = *(const float2*)&xsT[d][tb << 1];
            float4 wv = *(const float4*)&W[(d << 8) + e0];
            acc[0][0] += xv.x * wv.x; acc[0][1] += xv.x * wv.y;
            acc[0][2] += xv.x * wv.z; acc[0][3] += xv.x * wv.w;
            acc[1][0] += xv.y * wv.x; acc[1][1] += xv.y * wv.y;
            acc[1][2] += xv.y * wv.z; acc[1][3] += xv.y * wv.w;
        }
        int h = e0 >> 5, eo = e0 & 31;
        #pragma unroll
        for (int i = 0; i < 2; ++i) {
            int b = (tb << 1) + i;
            __half2 h0 = __floats2half2_rn(acc[i][0], acc[i][1]);
            __half2 h1 = __floats2half2_rn(acc[i][2], acc[i][3]);
            uint2 u;
            u.x = *(const unsigned int*)&h0;
            u.y = *(const unsigned int*)&h1;
            *(uint2*)&g_v16[(((size_t)(h * B_ + b) * T_ + t) << 4) + (eo >> 1)] = u;
        }
    }
}

// ---------------- K4: mixing coefficients (half2 out) ----------------
__global__ void k4_mix(const float* __restrict__ A, const float* __restrict__ L) {
    int t = blockIdx.x, c = threadIdx.x;
    int j0 = c << 1, j1 = j0 + 1;
    float a0 = 0.5f * (A[t * T_ + j0] + A[j0 * T_ + t]);
    float a1 = 0.5f * (A[t * T_ + j1] + A[j1 * T_ + t]);
    float lam0 = 1.0f / (1.0f + __expf(-L[t * T_ + j0]));
    float lam1 = 1.0f / (1.0f + __expf(-L[t * T_ + j1]));
    g_lamA2[t * 256 + c] = __floats2half2_rn(lam0 * a0, lam1 * a1);
    g_oml2[t * 256 + c]  = __floats2half2_rn(1.0f - lam0, 1.0f - lam1);
}

// ---------------- K57: fused scores+softmax+mix+symexp+Sinkhorn+PV ----------------
#define SM_UNION 131072
#define SM_Y     196864
#define SM_UL    200960
#define SMEM57   201472
#define NW_      32       // warps per CTA
#define HSTEPS_  24       // 12 Sinkhorn iterations (converged to ~2e-13; 20 iters redundant)

#define CBAR() do { \
    asm volatile("barrier.cluster.arrive.aligned;" ::: "memory"); \
    asm volatile("barrier.cluster.wait.aligned;"  ::: "memory"); } while (0)

__global__ __launch_bounds__(1024) __cluster_dims__(4, 1, 1)
void k57(float* __restrict__ out) {
    extern __shared__ char sm[];
    __half2* tile = (__half2*)sm;                 // [128][256] half2 = M/E rows fp16
    float2*  kT2  = (float2*)(sm + SM_UNION);     // [32][257] float2 (phase 1-2)
    float*   Vs   = (float*)(sm + SM_UNION);      // [512][32] f32 (phase 5-6)
    float*   s_y  = (float*)(sm + SM_Y);          // [2][512]
    float*   s_ul = (float*)(sm + SM_UL);         // [128]

    int tid = threadIdx.x;
    int hb = blockIdx.x >> 2;
    int rank = blockIdx.x & 3;
    int warp = tid >> 5, lane = tid & 31;

    unsigned sbase;
    asm("{ .reg .u64 t; cvta.to.shared.u64 t, %1; cvt.u32.u64 %0, t; }"
        : "=r"(sbase) : "l"(sm));

    // ---- phase 1: K transpose into kT2 ----
    const float* K = g_k + hb * (T_ * E_);
    for (int idx = tid; idx < T_ * E_; idx += 1024) {
        int t = idx >> 5, e = idx & 31;
        ((float*)&kT2[e * 257 + (t >> 1)])[t & 1] = K[idx];
    }
    __syncthreads();

    // ---- phase 2: scores + softmax + mix -> tile (fp16 M, local rows) ----
    {
        const float* Q = g_q + hb * (T_ * E_);
        const float SC = 0.17677669529663687f;
        for (int p = warp; p < 64; p += NW_) {
            int i0 = p << 1, i1 = i0 + 1;
            int gi0 = (rank << 7) + i0, gi1 = gi0 + 1;
            float q0 = Q[(gi0 << 5) + lane];
            float q1 = Q[(gi1 << 5) + lane];
            float a[8][4];
            #pragma unroll
            for (int m = 0; m < 8; ++m) { a[m][0] = a[m][1] = a[m][2] = a[m][3] = 0.f; }
            #pragma unroll
            for (int d = 0; d < 32; ++d) {
                float qd0 = __shfl_sync(0xffffffffu, q0, d);
                float qd1 = __shfl_sync(0xffffffffu, q1, d);
                const float2* row = &kT2[d * 257];
                #pragma unroll
                for (int m = 0; m < 8; ++m) {
                    float2 kv = row[lane + (m << 5)];
                    a[m][0] += qd0 * kv.x; a[m][1] += qd0 * kv.y;
                    a[m][2] += qd1 * kv.x; a[m][3] += qd1 * kv.y;
                }
            }
            float mx0 = -1e30f, mx1 = -1e30f;
            #pragma unroll
            for (int m = 0; m < 8; ++m) {
                a[m][0] *= SC; a[m][1] *= SC; a[m][2] *= SC; a[m][3] *= SC;
                mx0 = fmaxf(mx0, fmaxf(a[m][0], a[m][1]));
                mx1 = fmaxf(mx1, fmaxf(a[m][2], a[m][3]));
            }
            #pragma unroll
            for (int o = 16; o; o >>= 1) {
                mx0 = fmaxf(mx0, __shfl_xor_sync(0xffffffffu, mx0, o));
                mx1 = fmaxf(mx1, __shfl_xor_sync(0xffffffffu, mx1, o));
            }
            float sm0 = 0.f, sm1 = 0.f;
            #pragma unroll
            for (int m = 0; m < 8; ++m) {
                a[m][0] = __expf(a[m][0] - mx0); a[m][1] = __expf(a[m][1] - mx0);
                a[m][2] = __expf(a[m][2] - mx1); a[m][3] = __expf(a[m][3] - mx1);
                sm0 += a[m][0] + a[m][1];
                sm1 += a[m][2] + a[m][3];
            }
            #pragma unroll
            for (int o = 16; o; o >>= 1) {
                sm0 += __shfl_xor_sync(0xffffffffu, sm0, o);
                sm1 += __shfl_xor_sync(0xffffffffu, sm1, o);
            }
            float in0 = 1.0f / sm0, in1 = 1.0f / sm1;
            #pragma unroll
            for (int m = 0; m < 8; ++m) {
                int c = lane + (m << 5);
                float2 la0 = __half22float2(g_lamA2[gi0 * 256 + c]);
                float2 om0 = __half22float2(g_oml2[gi0 * 256 + c]);
                float2 la1 = __half22float2(g_lamA2[gi1 * 256 + c]);
                float2 om1 = __half22float2(g_oml2[gi1 * 256 + c]);
                tile[(i0 << 8) + c] = __floats2half2_rn(la0.x + om0.x * (a[m][0] * in0),
                                                        la0.y + om0.y * (a[m][1] * in0));
                tile[(i1 << 8) + c] = __floats2half2_rn(la1.x + om1.x * (a[m][2] * in1),
                                                        la1.y + om1.y * (a[m][3] * in1));
            }
        }
    }
    __syncthreads();
    CBAR();   // all cluster tiles hold M

    // ---- phase 3: symmetrize + exp (DSMEM peer reads, reg-staged) ----
    {
        int i0 = (tid & 15) << 3;    // 8 rows
        int j0 = (tid >> 4) << 3;    // 8 cols (64 groups)
        uint4 pv[8];
        #pragma unroll
        for (int jj = 0; jj < 8; ++jj) {
            int j = j0 + jj;
            unsigned laddr = sbase + (unsigned)((((j & 127) << 9) + (rank << 7) + i0) << 1);
            unsigned raddr;
            asm volatile("mapa.shared::cluster.u32 %0, %1, %2;"
                         : "=r"(raddr) : "r"(laddr), "r"(j >> 7));
            asm volatile("ld.shared::cluster.v4.u32 {%0,%1,%2,%3}, [%4];"
                         : "=r"(pv[jj].x), "=r"(pv[jj].y), "=r"(pv[jj].z), "=r"(pv[jj].w)
                         : "r"(raddr));
        }
        CBAR();   // all reads done -> safe to overwrite
        #pragma unroll
        for (int ii = 0; ii < 8; ++ii) {
            int i = i0 + ii;
            __half2* rowp = &tile[(i << 8) + (j0 >> 1)];
            uint4 o0 = *(const uint4*)rowp;
            __half oh[8];
            *(uint4*)&oh[0] = o0;
            __half rh[8];
            #pragma unroll
            for (int jj = 0; jj < 8; ++jj) {
                float pe = __half2float(((const __half*)&pv[jj])[ii]);
                float ow = __half2float(oh[jj]);
                rh[jj] = __float2half_rn(__expf(0.5f * (ow + pe)));
            }
            *(uint4*)rowp = *(const uint4*)&rh[0];
        }
    }
    if (tid < 512) s_y[tid] = 1.0f;   // buffer 0 = ev_init
    __syncthreads();

    // ---- phase 4: Sinkhorn, HSTEPS_ half-steps (uint4 + HFMA2 chunks) ----
    int cur = 0;
    for (int hstep = 0; hstep < HSTEPS_; ++hstep) {
        const float* yb = &s_y[cur << 9];
        float4 ya0 = *(const float4*)&yb[lane * 8];
        float4 ya1 = *(const float4*)&yb[lane * 8 + 4];
        float4 yb0 = *(const float4*)&yb[256 + lane * 8];
        float4 yb1 = *(const float4*)&yb[256 + lane * 8 + 4];
        __half2 yh0 = __floats2half2_rn(ya0.x, ya0.y);
        __half2 yh1 = __floats2half2_rn(ya0.z, ya0.w);
        __half2 yh2 = __floats2half2_rn(ya1.x, ya1.y);
        __half2 yh3 = __floats2half2_rn(ya1.z, ya1.w);
        __half2 yh4 = __floats2half2_rn(yb0.x, yb0.y);
        __half2 yh5 = __floats2half2_rn(yb0.z, yb0.w);
        __half2 yh6 = __floats2half2_rn(yb1.x, yb1.y);
        __half2 yh7 = __floats2half2_rn(yb1.z, yb1.w);

        int nxt = cur ^ 1;
        for (int i = warp; i < 128; i += NW_) {
            const uint4* rowq = (const uint4*)(tile + (i << 8));
            uint4 ea = rowq[lane];
            uint4 eb = rowq[lane + 32];
            __half2 a0 = __hmul2(*(const __half2*)&ea.x, yh0);
            a0 = __hfma2(*(const __half2*)&ea.y, yh1, a0);
            a0 = __hfma2(*(const __half2*)&ea.z, yh2, a0);
            a0 = __hfma2(*(const __half2*)&ea.w, yh3, a0);
            __half2 a1 = __hmul2(*(const __half2*)&eb.x, yh4);
            a1 = __hfma2(*(const __half2*)&eb.y, yh5, a1);
            a1 = __hfma2(*(const __half2*)&eb.z, yh6, a1);
            a1 = __hfma2(*(const __half2*)&eb.w, yh7, a1);
            float2 f0 = __half22float2(a0);
            float2 f1 = __half22float2(a1);
            float acc = f0.x + f0.y + f1.x + f1.y;
            #pragma unroll
            for (int o = 16; o; o >>= 1) acc += __shfl_xor_sync(0xffffffffu, acc, o);
            if (lane == 0) {
                float r = 1.0f / acc;
                if (!(hstep & 1)) s_ul[i] = r;
                unsigned laddr = sbase + (unsigned)(SM_Y + (((nxt << 9) + (rank << 7) + i) << 2));
                #pragma unroll
                for (int tr = 0; tr < 4; ++tr) {
                    unsigned raddr;
                    asm volatile("mapa.shared::cluster.u32 %0, %1, %2;"
                                 : "=r"(raddr) : "r"(laddr), "r"(tr));
                    asm volatile("st.shared::cluster.f32 [%0], %1;"
                                 :: "r"(raddr), "f"(r) : "memory");
                }
            }
        }
        CBAR();
        cur ^= 1;
    }
    // s_y[cur] = final ev (512), s_ul = final eu (local 128)

    // ---- phase 5: Vs fp32 = V * ev ----
    {
        const __half2* V16 = g_v16 + hb * 8192;
        const float* evf = &s_y[cur << 9];
        for (int idx = tid; idx < 8192; idx += 1024) {
            int j = idx >> 4, c2 = idx & 15;
            float2 v = __half22float2(V16[idx]);
            float e = evf[j];
            Vs[(j << 5) + (c2 << 1)]     = v.x * e;
            Vs[(j << 5) + (c2 << 1) + 1] = v.y * e;
        }
    }
    __syncthreads();

    // ---- phase 6: out = eu * (E @ Vs), 4 rows per warp ----
    {
        float acc[4];
        #pragma unroll
        for (int r = 0; r < 4; ++r) acc[r] = 0.f;
        const __half2* trow = tile + ((warp << 2) << 8);
        #pragma unroll 2
        for (int c = 0; c < 256; ++c) {
            float vx = Vs[((c << 1) << 5) + lane];
            float vy = Vs[(((c << 1) + 1) << 5) + lane];
            #pragma unroll
            for (int r = 0; r < 4; ++r) {
                float2 p = __half22float2(trow[(r << 8) + c]);
                acc[r] += p.x * vx + p.y * vy;
            }
        }
        int h = hb >> 4, b = hb & 15;
        #pragma unroll
        for (int r = 0; r < 4; ++r) {
            int gi = (rank << 7) + (warp << 2) + r;
            out[(((size_t)(b * T_ + gi)) << 8) + (h << 5) + lane]
                = s_ul[(warp << 2) + r] * acc[r];
        }
    }
}

// ---------------- launch ----------------
extern "C" void kernel_launch(void* const* d_in, const int* in_sizes, int n_in,
                              void* d_out, int out_size) {
    const float* X  = (const float*)d_in[0];
    const float* te = (const float*)d_in[1];
    const float* Wq = (const float*)d_in[2];
    const float* Wk = (const float*)d_in[3];
    const float* Qb = (const float*)d_in[4];
    const float* Kb = (const float*)d_in[5];
    const float* WV = (const float*)d_in[6];
    const float* A  = (const float*)d_in[7];
    const float* L  = (const float*)d_in[8];
    float* out = (float*)d_out;

    cudaFuncSetAttribute(k57, cudaFuncAttributeMaxDynamicSharedMemorySize, SMEM57);

    k1_weights<<<T_, 256>>>(te, Wq, Wk);
    k2_tilde<<<dim3(64, 2, 8), 256>>>(Qb, Kb);
    k3_qkv<<<dim3(T_, 4), 256>>>(X, WV);
    k4_mix<<<T_, 256>>>(A, L);
    k57<<<HB_ * 4, 1024, SMEM57>>>(out);
}